// round 2
// baseline (speedup 1.0000x reference)
#include <cuda_runtime.h>
#include <cstdint>
#include <math.h>

// Problem constants
#define B_  256
#define E_  256
#define H_  512
#define V_  32768
#define T_  8
#define LN_EPS 1e-5f
#define RMS_EPS 1.1920928955078125e-7f   // finfo(f32).eps
#define TINY_F 1.17549435e-38f

// ---------------- device scratch (static, allocation-free) ----------------
__device__ float g_h[B_ * H_];        // current residual h [256,512]
__device__ float g_zinv[B_];          // 1/max(||h_b||, 1e-12)
__device__ float g_cinv[V_];          // 1/max(||C_v||, 1e-12)
__device__ float g_partial[64 * B_ * H_];  // split-K partials (33.5MB)
__device__ float g_probs[B_ * V_];    // fallback probs scratch (32MB)

// ---------------- reductions ----------------
__device__ __forceinline__ float blockReduceSum(float v, float* sh) {
    __syncthreads();
    int lane = threadIdx.x & 31, wid = threadIdx.x >> 5;
#pragma unroll
    for (int o = 16; o; o >>= 1) v += __shfl_xor_sync(0xFFFFFFFFu, v, o);
    if (lane == 0) sh[wid] = v;
    __syncthreads();
    int nw = blockDim.x >> 5;
    if (wid == 0) {
        float s = (lane < nw) ? sh[lane] : 0.f;
#pragma unroll
        for (int o = 16; o; o >>= 1) s += __shfl_xor_sync(0xFFFFFFFFu, s, o);
        if (lane == 0) sh[0] = s;
    }
    __syncthreads();
    float r = sh[0];
    __syncthreads();
    return r;
}

__device__ __forceinline__ float blockReduceMax(float v, float* sh) {
    __syncthreads();
    int lane = threadIdx.x & 31, wid = threadIdx.x >> 5;
#pragma unroll
    for (int o = 16; o; o >>= 1) v = fmaxf(v, __shfl_xor_sync(0xFFFFFFFFu, v, o));
    if (lane == 0) sh[wid] = v;
    __syncthreads();
    int nw = blockDim.x >> 5;
    if (wid == 0) {
        float s = (lane < nw) ? sh[lane] : -3.4e38f;
#pragma unroll
        for (int o = 16; o; o >>= 1) s = fmaxf(s, __shfl_xor_sync(0xFFFFFFFFu, s, o));
        if (lane == 0) sh[0] = s;
    }
    __syncthreads();
    float r = sh[0];
    __syncthreads();
    return r;
}

// ---------------- Threefry-2x32 (JAX PRNG, key = (0, 42)) ----------------
__device__ __forceinline__ unsigned rotl32(unsigned x, int r) {
    return __funnelshift_l(x, x, r);
}

__device__ __forceinline__ uint2 tf2x32(unsigned x0, unsigned x1) {
    const unsigned k0 = 0u, k1 = 42u;
    const unsigned k2 = k0 ^ k1 ^ 0x1BD11BDAu;
    x0 += k0; x1 += k1;
#define TFR(r) { x0 += x1; x1 = rotl32(x1, r); x1 ^= x0; }
    TFR(13) TFR(15) TFR(26) TFR(6)
    x0 += k1; x1 += k2 + 1u;
    TFR(17) TFR(29) TFR(16) TFR(24)
    x0 += k2; x1 += k0 + 2u;
    TFR(13) TFR(15) TFR(26) TFR(6)
    x0 += k0; x1 += k1 + 3u;
    TFR(17) TFR(29) TFR(16) TFR(24)
    x0 += k1; x1 += k2 + 4u;
    TFR(13) TFR(15) TFR(26) TFR(6)
    x0 += k2; x1 += k0 + 5u;
#undef TFR
    return make_uint2(x0, x1);
}

// gumbel[t,b,v] as jax.random.gumbel(key(42), (T,B,V), f32) with
// jax_threefry_partitionable=True (modern JAX default):
//   per-element 64-bit counter c = flat index f; count words (hi,lo) = (0, f)
//   bits32 = out0 ^ out1
__device__ __forceinline__ float gumbel_val(unsigned t, unsigned b, unsigned v) {
    unsigned f = (((t << 8) | b) << 15) | v;  // t*2^23 + b*2^15 + v  (< 2^26)
    uint2 r = tf2x32(0u, f);
    unsigned bits = r.x ^ r.y;
    unsigned m = bits >> 9;
    float u = (m == 0u) ? TINY_F : (__uint_as_float(0x3F800000u | m) - 1.0f);
    return -logf(-logf(u));
}

__device__ __forceinline__ float tau_value(const void* p) {
    int i = *(const int*)p;
    float f = __int_as_float(i);
    if (f > 1e-3f && f < 1e6f) return f;   // was stored as float
    return (float)i;                        // stored as int (expected: 1)
}

// ---------------- backbone: h = GELU(LN(x@W1 + b1)) ----------------
__global__ void __launch_bounds__(512) backbone_kernel(
    const float* __restrict__ x, const float* __restrict__ W1,
    const float* __restrict__ b1, const float* __restrict__ ln_g,
    const float* __restrict__ ln_b) {
    __shared__ float xs[E_];
    __shared__ float sred[32];
    int b = blockIdx.x, col = threadIdx.x;
    if (col < E_) xs[col] = x[b * E_ + col];
    __syncthreads();
    float acc = b1[col];
#pragma unroll 4
    for (int e = 0; e < E_; e++) acc = fmaf(xs[e], W1[e * H_ + col], acc);
    float mu = blockReduceSum(acc, sred) * (1.0f / H_);
    float d = acc - mu;
    float var = blockReduceSum(d * d, sred) * (1.0f / H_);
    float nrm = d / sqrtf(var + LN_EPS) * ln_g[col] + ln_b[col];
    float hv = 0.5f * nrm * (1.0f + erff(nrm * 0.70710678118654752f));
    g_h[b * H_ + col] = hv;
    float n2 = blockReduceSum(hv * hv, sred);
    if (col == 0) g_zinv[b] = 1.0f / fmaxf(sqrtf(n2), 1e-12f);
}

// ---------------- codebook row inverse norms ----------------
__global__ void __launch_bounds__(256) cinv_kernel(const float* __restrict__ C) {
    int warp = blockIdx.x * 8 + (threadIdx.x >> 5);
    int lane = threadIdx.x & 31;
    if (warp >= V_) return;
    const float* row = C + (size_t)warp * H_;
    float ss = 0.f;
#pragma unroll 4
    for (int i = lane; i < H_; i += 32) { float v = row[i]; ss = fmaf(v, v, ss); }
#pragma unroll
    for (int o = 16; o; o >>= 1) ss += __shfl_xor_sync(0xFFFFFFFFu, ss, o);
    if (lane == 0) g_cinv[warp] = 1.0f / fmaxf(sqrtf(ss), 1e-12f);
}

// ---------------- logits GEMM: out[b,t,v] = (h_b . C_v)*zinv*cinv*exp(ls[t]) ----------------
__global__ void __launch_bounds__(256) logits_gemm_kernel(
    const float* __restrict__ Cb, const float* __restrict__ lscale,
    float* __restrict__ out, int t) {
    __shared__ float As[16][128 + 4];  // [k][b]
    __shared__ float Bs[16][128 + 4];  // [k][v]
    const int tid = threadIdx.x;
    const int vbase = blockIdx.x * 128, bbase = blockIdx.y * 128;
    const int tx = tid & 15, ty = tid >> 4;
    float acc[8][8];
#pragma unroll
    for (int i = 0; i < 8; i++)
#pragma unroll
        for (int j = 0; j < 8; j++) acc[i][j] = 0.f;

    for (int k0 = 0; k0 < H_; k0 += 16) {
#pragma unroll
        for (int l = 0; l < 2; l++) {  // A = h tile [128b x 16k] -> As[k][b]
            int q = tid + l * 256, row = q >> 2, c4 = q & 3;
            float4 vv = *(const float4*)(g_h + (size_t)(bbase + row) * H_ + k0 + c4 * 4);
            As[c4 * 4 + 0][row] = vv.x; As[c4 * 4 + 1][row] = vv.y;
            As[c4 * 4 + 2][row] = vv.z; As[c4 * 4 + 3][row] = vv.w;
        }
#pragma unroll
        for (int l = 0; l < 2; l++) {  // B = C tile [128v x 16k] -> Bs[k][v]
            int q = tid + l * 256, row = q >> 2, c4 = q & 3;
            float4 vv = *(const float4*)(Cb + (size_t)(vbase + row) * H_ + k0 + c4 * 4);
            Bs[c4 * 4 + 0][row] = vv.x; Bs[c4 * 4 + 1][row] = vv.y;
            Bs[c4 * 4 + 2][row] = vv.z; Bs[c4 * 4 + 3][row] = vv.w;
        }
        __syncthreads();
#pragma unroll
        for (int k = 0; k < 16; k++) {
            float4 a0 = *(const float4*)&As[k][ty * 8];
            float4 a1 = *(const float4*)&As[k][ty * 8 + 4];
            float4 b0 = *(const float4*)&Bs[k][tx * 8];
            float4 b1 = *(const float4*)&Bs[k][tx * 8 + 4];
            float av[8] = {a0.x, a0.y, a0.z, a0.w, a1.x, a1.y, a1.z, a1.w};
            float bv[8] = {b0.x, b0.y, b0.z, b0.w, b1.x, b1.y, b1.z, b1.w};
#pragma unroll
            for (int i = 0; i < 8; i++)
#pragma unroll
                for (int j = 0; j < 8; j++) acc[i][j] = fmaf(av[i], bv[j], acc[i][j]);
        }
        __syncthreads();
    }
    float scale = expf(lscale[t]);
    float cv[8];
#pragma unroll
    for (int j = 0; j < 8; j++) cv[j] = g_cinv[vbase + tx * 8 + j] * scale;
#pragma unroll
    for (int i = 0; i < 8; i++) {
        int b = bbase + ty * 8 + i;
        float zb = g_zinv[b];
        float* orow = out + (((size_t)b * T_ + t) << 15) + vbase + tx * 8;
        float4 o0 = make_float4(acc[i][0] * zb * cv[0], acc[i][1] * zb * cv[1],
                                acc[i][2] * zb * cv[2], acc[i][3] * zb * cv[3]);
        float4 o1 = make_float4(acc[i][4] * zb * cv[4], acc[i][5] * zb * cv[5],
                                acc[i][6] * zb * cv[6], acc[i][7] * zb * cv[7]);
        *(float4*)orow = o0;
        *(float4*)(orow + 4) = o1;
    }
}

// ---------------- softmax with inline gumbel ----------------
__global__ void __launch_bounds__(1024) softmax_kernel(
    const float* __restrict__ out, float* __restrict__ outw,
    const void* __restrict__ taup, int t, int writeProbs) {
    __shared__ float sred[32];
    int b = blockIdx.x;
    const float* lrow = out + (((size_t)b * T_ + t) << 15);
    float* prow = writeProbs
        ? outw + (size_t)B_ * T_ * V_ + (((size_t)b * T_ + t) << 15)
        : g_probs + (size_t)b * V_;
    float inv_tau = 1.0f / tau_value(taup);
    float x[32];
    float m = -3.4e38f;
#pragma unroll
    for (int i = 0; i < 32; i++) {
        int v = threadIdx.x + i * 1024;
        float g = gumbel_val((unsigned)t, (unsigned)b, (unsigned)v);
        x[i] = (lrow[v] + g) * inv_tau;
        m = fmaxf(m, x[i]);
    }
    m = blockReduceMax(m, sred);
    float s = 0.f;
#pragma unroll
    for (int i = 0; i < 32; i++) {
        float e = expf(x[i] - m);
        x[i] = e;
        s += e;
    }
    s = blockReduceSum(s, sred);
    float r = 1.0f / s;
#pragma unroll
    for (int i = 0; i < 32; i++) prow[threadIdx.x + i * 1024] = x[i] * r;
}

// ---------------- expected GEMM (split-K, deterministic) ----------------
__global__ void __launch_bounds__(256) expected_gemm_kernel(
    const float* __restrict__ out, const float* __restrict__ Cb,
    int t, int writeProbs) {
    __shared__ float As[16][128 + 4];  // [k][b]  probs
    __shared__ float Bs[16][128 + 4];  // [k][h]  codebook
    const int tid = threadIdx.x;
    const int hbase = blockIdx.x * 128, bbase = blockIdx.y * 128;
    const int kbase = blockIdx.z * 512;
    const int tx = tid & 15, ty = tid >> 4;

    const float* pbase;
    size_t pstride;
    if (writeProbs) {
        pbase = out + (size_t)B_ * T_ * V_ + (size_t)t * V_;
        pstride = (size_t)T_ * V_;
    } else {
        pbase = g_probs;
        pstride = V_;
    }

    float acc[8][8];
#pragma unroll
    for (int i = 0; i < 8; i++)
#pragma unroll
        for (int j = 0; j < 8; j++) acc[i][j] = 0.f;

    for (int k0 = 0; k0 < 512; k0 += 16) {
        int kk = kbase + k0;
#pragma unroll
        for (int l = 0; l < 2; l++) {  // probs tile [128b x 16k] -> As[k][b]
            int q = tid + l * 256, row = q >> 2, c4 = q & 3;
            float4 vv = *(const float4*)(pbase + (size_t)(bbase + row) * pstride + kk + c4 * 4);
            As[c4 * 4 + 0][row] = vv.x; As[c4 * 4 + 1][row] = vv.y;
            As[c4 * 4 + 2][row] = vv.z; As[c4 * 4 + 3][row] = vv.w;
        }
#pragma unroll
        for (int l = 0; l < 2; l++) {  // C tile [16k x 128h] -> Bs[k][h]
            int q = tid + l * 256, row = q >> 5, c = q & 31;
            float4 vv = *(const float4*)(Cb + (size_t)(kk + row) * H_ + hbase + c * 4);
            *(float4*)&Bs[row][c * 4] = vv;
        }
        __syncthreads();
#pragma unroll
        for (int k = 0; k < 16; k++) {
            float4 a0 = *(const float4*)&As[k][ty * 8];
            float4 a1 = *(const float4*)&As[k][ty * 8 + 4];
            float4 b0 = *(const float4*)&Bs[k][tx * 8];
            float4 b1 = *(const float4*)&Bs[k][tx * 8 + 4];
            float av[8] = {a0.x, a0.y, a0.z, a0.w, a1.x, a1.y, a1.z, a1.w};
            float bv[8] = {b0.x, b0.y, b0.z, b0.w, b1.x, b1.y, b1.z, b1.w};
#pragma unroll
            for (int i = 0; i < 8; i++)
#pragma unroll
                for (int j = 0; j < 8; j++) acc[i][j] = fmaf(av[i], bv[j], acc[i][j]);
        }
        __syncthreads();
    }
#pragma unroll
    for (int i = 0; i < 8; i++) {
        int b = bbase + ty * 8 + i;
        float* p = g_partial + (((size_t)blockIdx.z * B_ + b) << 9) + hbase + tx * 8;
        float4 o0 = make_float4(acc[i][0], acc[i][1], acc[i][2], acc[i][3]);
        float4 o1 = make_float4(acc[i][4], acc[i][5], acc[i][6], acc[i][7]);
        *(float4*)p = o0;
        *(float4*)(p + 4) = o1;
    }
}

// ---------------- residual update + RMSNorm ----------------
__global__ void __launch_bounds__(512) update_kernel(
    const float* __restrict__ gamma, const float* __restrict__ rms_w, int t) {
    __shared__ float sred[32];
    int b = blockIdx.x, h = threadIdx.x;
    float e = 0.f;
#pragma unroll
    for (int s = 0; s < 64; s++) e += g_partial[((size_t)s * B_ + b) * H_ + h];
    float eg = expf(gamma[t]);
    float hn = g_h[b * H_ + h] - eg * e;
    float ss = blockReduceSum(hn * hn, sred);
    float denom = sqrtf(ss * (1.0f / H_) + RMS_EPS);
    float hv = hn / denom * rms_w[h];
    g_h[b * H_ + h] = hv;
    float n2 = blockReduceSum(hv * hv, sred);
    if (h == 0) g_zinv[b] = 1.0f / fmaxf(sqrtf(n2), 1e-12f);
}

// ---------------- launch ----------------
extern "C" void kernel_launch(void* const* d_in, const int* in_sizes, int n_in,
                              void* d_out, int out_size) {
    const float* x           = (const float*)d_in[0];
    const float* W1          = (const float*)d_in[1];
    const float* b1          = (const float*)d_in[2];
    const float* ln_g        = (const float*)d_in[3];
    const float* ln_b        = (const float*)d_in[4];
    const float* codebook    = (const float*)d_in[5];
    const float* logit_scale = (const float*)d_in[6];
    const float* gamma       = (const float*)d_in[7];
    const float* rms_w       = (const float*)d_in[8];
    const void*  tau         = d_in[9];
    float* out = (float*)d_out;

    const long long logitsElems = (long long)B_ * T_ * V_;  // 67108864
    int writeProbs = ((long long)out_size >= 2 * logitsElems) ? 1 : 0;

    backbone_kernel<<<B_, 512>>>(x, W1, b1, ln_g, ln_b);
    cinv_kernel<<<V_ / 8, 256>>>(codebook);

    for (int t = 0; t < T_; t++) {
        logits_gemm_kernel<<<dim3(V_ / 128, B_ / 128), 256>>>(codebook, logit_scale, out, t);
        softmax_kernel<<<B_, 1024>>>(out, out, tau, t, writeProbs);
        if (t < T_ - 1) {
            expected_gemm_kernel<<<dim3(H_ / 128, B_ / 128, 64), 256>>>(out, codebook, t, writeProbs);
            update_kernel<<<B_, 512>>>(gamma, rms_w, t);
        }
    }
}

// round 5
// speedup vs baseline: 2.8821x; 2.8821x over previous
#include <cuda_runtime.h>
#include <cuda_bf16.h>
#include <cstdint>
#include <math.h>

// Problem constants
#define B_  256
#define E_  256
#define H_  512
#define V_  32768
#define T_  8
#define LN_EPS 1e-5f
#define RMS_EPS 1.1920928955078125e-7f   // finfo(f32).eps
#define TINY_F 1.17549435e-38f

#define ZSPLIT 32                         // split-K factor for expected GEMM

// ---------------- device scratch (static, allocation-free) ----------------
__device__ __align__(16) float g_h[B_ * H_];                 // residual h (fp32 exact)
__device__ __align__(16) __nv_bfloat16 g_h_hi[B_ * H_];
__device__ __align__(16) __nv_bfloat16 g_h_lo[B_ * H_];
__device__ float g_zinv[B_];
__device__ float g_cinv[V_];
__device__ __align__(16) __nv_bfloat16 g_C_hi[(size_t)V_ * H_];   // codebook hi  [V][H]
__device__ __align__(16) __nv_bfloat16 g_C_lo[(size_t)V_ * H_];   // codebook lo  [V][H]
__device__ __align__(16) __nv_bfloat16 g_CT[(size_t)H_ * V_];     // codebook^T bf16 [H][V]
__device__ __align__(16) __nv_bfloat16 g_probs_bf16[(size_t)B_ * V_];
__device__ __align__(16) float g_partial[ZSPLIT * B_ * H_];       // split-K partials

// ================= PTX helpers (base ISA only: sm_80-level, works on compute_103) =================
__device__ __forceinline__ uint32_t smem_u32(const void* p) {
    uint32_t a;
    asm("{ .reg .u64 t; cvta.to.shared.u64 t, %1; cvt.u32.u64 %0, t; }" : "=r"(a) : "l"(p));
    return a;
}
__device__ __forceinline__ void cp16(uint32_t dst, const void* src) {
    asm volatile("cp.async.cg.shared.global [%0], [%1], 16;" :: "r"(dst), "l"(src) : "memory");
}
#define CP_COMMIT() asm volatile("cp.async.commit_group;" ::: "memory")
#define CP_WAIT1()  asm volatile("cp.async.wait_group 1;" ::: "memory")

__device__ __forceinline__ void ldsm4(uint32_t* r, uint32_t addr) {
    asm volatile("ldmatrix.sync.aligned.m8n8.x4.shared.b16 {%0,%1,%2,%3}, [%4];"
                 : "=r"(r[0]), "=r"(r[1]), "=r"(r[2]), "=r"(r[3]) : "r"(addr));
}
__device__ __forceinline__ void mma_bf16(float* d, const uint32_t* a, const uint32_t* b) {
    asm volatile(
        "mma.sync.aligned.m16n8k16.row.col.f32.bf16.bf16.f32 "
        "{%0,%1,%2,%3}, {%4,%5,%6,%7}, {%8,%9}, {%0,%1,%2,%3};"
        : "+f"(d[0]), "+f"(d[1]), "+f"(d[2]), "+f"(d[3])
        : "r"(a[0]), "r"(a[1]), "r"(a[2]), "r"(a[3]), "r"(b[0]), "r"(b[1]));
}

// ---------------- reductions ----------------
__device__ __forceinline__ float blockReduceSum(float v, float* sh) {
    __syncthreads();
    int lane = threadIdx.x & 31, wid = threadIdx.x >> 5;
#pragma unroll
    for (int o = 16; o; o >>= 1) v += __shfl_xor_sync(0xFFFFFFFFu, v, o);
    if (lane == 0) sh[wid] = v;
    __syncthreads();
    int nw = blockDim.x >> 5;
    if (wid == 0) {
        float s = (lane < nw) ? sh[lane] : 0.f;
#pragma unroll
        for (int o = 16; o; o >>= 1) s += __shfl_xor_sync(0xFFFFFFFFu, s, o);
        if (lane == 0) sh[0] = s;
    }
    __syncthreads();
    float r = sh[0];
    __syncthreads();
    return r;
}
__device__ __forceinline__ float blockReduceMax(float v, float* sh) {
    __syncthreads();
    int lane = threadIdx.x & 31, wid = threadIdx.x >> 5;
#pragma unroll
    for (int o = 16; o; o >>= 1) v = fmaxf(v, __shfl_xor_sync(0xFFFFFFFFu, v, o));
    if (lane == 0) sh[wid] = v;
    __syncthreads();
    int nw = blockDim.x >> 5;
    if (wid == 0) {
        float s = (lane < nw) ? sh[lane] : -3.4e38f;
#pragma unroll
        for (int o = 16; o; o >>= 1) s = fmaxf(s, __shfl_xor_sync(0xFFFFFFFFu, s, o));
        if (lane == 0) sh[0] = s;
    }
    __syncthreads();
    float r = sh[0];
    __syncthreads();
    return r;
}

// ---------------- Threefry-2x32 (JAX partitionable, key=(0,42)) ----------------
__device__ __forceinline__ unsigned rotl32(unsigned x, int r) { return __funnelshift_l(x, x, r); }
__device__ __forceinline__ uint2 tf2x32(unsigned x0, unsigned x1) {
    const unsigned k0 = 0u, k1 = 42u;
    const unsigned k2 = k0 ^ k1 ^ 0x1BD11BDAu;
    x0 += k0; x1 += k1;
#define TFR(r) { x0 += x1; x1 = rotl32(x1, r); x1 ^= x0; }
    TFR(13) TFR(15) TFR(26) TFR(6)
    x0 += k1; x1 += k2 + 1u;
    TFR(17) TFR(29) TFR(16) TFR(24)
    x0 += k2; x1 += k0 + 2u;
    TFR(13) TFR(15) TFR(26) TFR(6)
    x0 += k0; x1 += k1 + 3u;
    TFR(17) TFR(29) TFR(16) TFR(24)
    x0 += k1; x1 += k2 + 4u;
    TFR(13) TFR(15) TFR(26) TFR(6)
    x0 += k2; x1 += k0 + 5u;
#undef TFR
    return make_uint2(x0, x1);
}
// NOTE: must use PRECISE logf here. gumbel = -log(-log(u)); for u near 1,
// -log(u) is tiny and __logf's absolute error becomes a large relative error,
// corrupting exactly the dominant (largest-gumbel) softmax entries.
__device__ __forceinline__ float gumbel_val(unsigned t, unsigned b, unsigned v) {
    unsigned f = (((t << 8) | b) << 15) | v;
    uint2 r = tf2x32(0u, f);
    unsigned bits = r.x ^ r.y;
    unsigned m = bits >> 9;
    float u = (m == 0u) ? TINY_F : (__uint_as_float(0x3F800000u | m) - 1.0f);
    return -logf(-logf(u));
}
__device__ __forceinline__ float tau_value(const void* p) {
    int i = *(const int*)p;
    float f = __int_as_float(i);
    if (f > 1e-3f && f < 1e6f) return f;
    return (float)i;
}

// ---------------- backbone: h = GELU(LN(x@W1 + b1)) ----------------
__global__ void __launch_bounds__(512) backbone_kernel(
    const float* __restrict__ x, const float* __restrict__ W1,
    const float* __restrict__ b1, const float* __restrict__ ln_g,
    const float* __restrict__ ln_b) {
    __shared__ float xs[E_];
    __shared__ float sred[32];
    int b = blockIdx.x, col = threadIdx.x;
    if (col < E_) xs[col] = x[b * E_ + col];
    __syncthreads();
    float acc = b1[col];
#pragma unroll 4
    for (int e = 0; e < E_; e++) acc = fmaf(xs[e], W1[e * H_ + col], acc);
    float mu = blockReduceSum(acc, sred) * (1.0f / H_);
    float d = acc - mu;
    float var = blockReduceSum(d * d, sred) * (1.0f / H_);
    float nrm = d / sqrtf(var + LN_EPS) * ln_g[col] + ln_b[col];
    float hv = 0.5f * nrm * (1.0f + erff(nrm * 0.70710678118654752f));
    g_h[b * H_ + col] = hv;
    __nv_bfloat16 hi = __float2bfloat16(hv);
    g_h_hi[b * H_ + col] = hi;
    g_h_lo[b * H_ + col] = __float2bfloat16(hv - __bfloat162float(hi));
    float n2 = blockReduceSum(hv * hv, sred);
    if (col == 0) g_zinv[b] = 1.0f / fmaxf(sqrtf(n2), 1e-12f);
}

// ---------------- codebook row inverse norms ----------------
__global__ void __launch_bounds__(256) cinv_kernel(const float* __restrict__ C) {
    int warp = blockIdx.x * 8 + (threadIdx.x >> 5);
    int lane = threadIdx.x & 31;
    if (warp >= V_) return;
    const float* row = C + (size_t)warp * H_;
    float ss = 0.f;
#pragma unroll 4
    for (int i = lane; i < H_; i += 32) { float v = row[i]; ss = fmaf(v, v, ss); }
#pragma unroll
    for (int o = 16; o; o >>= 1) ss += __shfl_xor_sync(0xFFFFFFFFu, ss, o);
    if (lane == 0) g_cinv[warp] = 1.0f / fmaxf(sqrtf(ss), 1e-12f);
}

// ---------------- codebook prep: bf16 hi/lo + bf16 transpose ----------------
__global__ void __launch_bounds__(256) prep_kernel(const float* __restrict__ C) {
    __shared__ float tile[32][33];
    int v0 = blockIdx.x * 32, h0 = blockIdx.y * 32;
    int tx = threadIdx.x & 31, ty = threadIdx.x >> 5;
#pragma unroll
    for (int j = 0; j < 4; j++) {
        int v = v0 + ty + j * 8;
        float val = C[(size_t)v * H_ + h0 + tx];
        __nv_bfloat16 hi = __float2bfloat16(val);
        g_C_hi[(size_t)v * H_ + h0 + tx] = hi;
        g_C_lo[(size_t)v * H_ + h0 + tx] = __float2bfloat16(val - __bfloat162float(hi));
        tile[ty + j * 8][tx] = val;
    }
    __syncthreads();
#pragma unroll
    for (int j = 0; j < 4; j++) {
        int h = h0 + ty + j * 8;
        g_CT[(size_t)h * V_ + v0 + tx] = __float2bfloat16(tile[tx][ty + j * 8]);
    }
}

// ================= logits GEMM (mma.sync bf16, hi/lo 3-pass) =================
// D[128b, 128v] per CTA = h[128,512] . C[v-tile]^T; epi: * zinv * cinv * exp(ls)
// smem: 2 stages x (Ah 16K | Al 16K | Bh 16K | Bl 16K) = 128KB, XOR swizzle.
#define LG_SMEM 131072
__global__ void __launch_bounds__(256) logits_mma_kernel(
    const float* __restrict__ lscale, float* __restrict__ out, int t) {
    extern __shared__ char smem[];
    const uint32_t sb = smem_u32(smem);
    const int tid = threadIdx.x, lane = tid & 31, wid = tid >> 5;
    const int wm = wid >> 2, wn = wid & 3;
    const int bbase = blockIdx.x * 128, vbase = blockIdx.y * 128;

    float acc[4][4][4];
#pragma unroll
    for (int i = 0; i < 4; i++)
#pragma unroll
        for (int j = 0; j < 4; j++)
#pragma unroll
            for (int c = 0; c < 4; c++) acc[i][j][c] = 0.f;

    // loader indices (per thread): 4 chunks per tile per stage
    const int lr = tid >> 3;            // base row (0..31), +32*i
    const int lc = tid & 7;             // 16B chunk col (0..7)

#define LOAD_STAGE(s, k0) do { \
        uint32_t st_ = sb + (s) * 65536; \
        _Pragma("unroll") \
        for (int i_ = 0; i_ < 4; i_++) { \
            int r_ = lr + i_ * 32; \
            uint32_t sw_ = ((uint32_t)(r_ * 128 + lc * 16)) ^ (((uint32_t)r_ & 7u) << 4); \
            size_t ga_ = (size_t)(bbase + r_) * H_ + (k0) + lc * 8; \
            size_t gb_ = (size_t)(vbase + r_) * H_ + (k0) + lc * 8; \
            cp16(st_ + sw_,         g_h_hi + ga_); \
            cp16(st_ + 16384 + sw_, g_h_lo + ga_); \
            cp16(st_ + 32768 + sw_, g_C_hi + gb_); \
            cp16(st_ + 49152 + sw_, g_C_lo + gb_); \
        } \
        CP_COMMIT(); \
    } while (0)

    LOAD_STAGE(0, 0);
    LOAD_STAGE(1, 64);

    // ldmatrix per-lane address pieces
    const int arow = wm * 64 + (lane & 7) + ((lane >> 3) & 1) * 8;  // + mi*16
    const int acol = (lane >> 4);                                    // 16B chunk, + ks*2
    const int brow = wn * 32 + (lane & 7) + (lane >> 4) * 8;         // + nj*16
    const int bcol = ((lane >> 3) & 1);                              // + ks*2

    for (int kt = 0; kt < 8; kt++) {
        CP_WAIT1();
        __syncthreads();
        uint32_t st = sb + (kt & 1) * 65536;
#pragma unroll
        for (int ks = 0; ks < 4; ks++) {
            uint32_t ah[4][4], al[4][4], bh[2][4], bl[2][4];
#pragma unroll
            for (int mi = 0; mi < 4; mi++) {
                int r = arow + mi * 16;
                uint32_t off = ((uint32_t)(r * 128 + (acol + ks * 2) * 16)) ^ (((uint32_t)r & 7u) << 4);
                ldsm4(ah[mi], st + off);
                ldsm4(al[mi], st + 16384 + off);
            }
#pragma unroll
            for (int nj = 0; nj < 2; nj++) {
                int r = brow + nj * 16;
                uint32_t off = ((uint32_t)(r * 128 + (bcol + ks * 2) * 16)) ^ (((uint32_t)r & 7u) << 4);
                ldsm4(bh[nj], st + 32768 + off);
                ldsm4(bl[nj], st + 49152 + off);
            }
#pragma unroll
            for (int mi = 0; mi < 4; mi++)
#pragma unroll
                for (int nf = 0; nf < 4; nf++) {
                    const uint32_t* bhp = &bh[nf >> 1][(nf & 1) * 2];
                    const uint32_t* blp = &bl[nf >> 1][(nf & 1) * 2];
                    mma_bf16(acc[mi][nf], ah[mi], bhp);
                    mma_bf16(acc[mi][nf], ah[mi], blp);
                    mma_bf16(acc[mi][nf], al[mi], bhp);
                }
        }
        __syncthreads();
        if (kt < 6) LOAD_STAGE(kt & 1, (kt + 2) * 64);
        else CP_COMMIT();  // empty group keeps wait_group accounting aligned
    }
#undef LOAD_STAGE

    // epilogue
    float scale = expf(__ldg(lscale + t));
#pragma unroll
    for (int mi = 0; mi < 4; mi++) {
        int r0 = bbase + wm * 64 + mi * 16 + (lane >> 2);
        float z0 = g_zinv[r0], z1 = g_zinv[r0 + 8];
        float* row0 = out + (((size_t)r0 * T_ + t) << 15);
        float* row1 = out + (((size_t)(r0 + 8) * T_ + t) << 15);
#pragma unroll
        for (int nf = 0; nf < 4; nf++) {
            int v0 = vbase + wn * 32 + nf * 8 + (lane & 3) * 2;
            float cv0 = g_cinv[v0] * scale, cv1 = g_cinv[v0 + 1] * scale;
            float2 w0 = make_float2(acc[mi][nf][0] * z0 * cv0, acc[mi][nf][1] * z0 * cv1);
            float2 w1 = make_float2(acc[mi][nf][2] * z1 * cv0, acc[mi][nf][3] * z1 * cv1);
            *(float2*)(row0 + v0) = w0;
            *(float2*)(row1 + v0) = w1;
        }
    }
}

// ================= expected GEMM (mma.sync bf16, split-K=32) =================
// partial[z][128b, 128h] = probs[128, kz:kz+1024] . CT-tile
#define EX_SMEM 65536
__global__ void __launch_bounds__(256) expected_mma_kernel() {
    extern __shared__ char smem[];
    const uint32_t sb = smem_u32(smem);
    const int tid = threadIdx.x, lane = tid & 31, wid = tid >> 5;
    const int wm = wid >> 2, wn = wid & 3;
    const int hbase = blockIdx.x * 128, bbase = blockIdx.y * 128;
    const int z = blockIdx.z;
    const int kz = z * (V_ / ZSPLIT);   // 1024

    float acc[4][4][4];
#pragma unroll
    for (int i = 0; i < 4; i++)
#pragma unroll
        for (int j = 0; j < 4; j++)
#pragma unroll
            for (int c = 0; c < 4; c++) acc[i][j][c] = 0.f;

    const int lr = tid >> 3;
    const int lc = tid & 7;

#define LOAD_STAGE(s, k0) do { \
        uint32_t st_ = sb + (s) * 32768; \
        _Pragma("unroll") \
        for (int i_ = 0; i_ < 4; i_++) { \
            int r_ = lr + i_ * 32; \
            uint32_t sw_ = ((uint32_t)(r_ * 128 + lc * 16)) ^ (((uint32_t)r_ & 7u) << 4); \
            cp16(st_ + sw_,         g_probs_bf16 + (size_t)(bbase + r_) * V_ + (k0) + lc * 8); \
            cp16(st_ + 16384 + sw_, g_CT         + (size_t)(hbase + r_) * V_ + (k0) + lc * 8); \
        } \
        CP_COMMIT(); \
    } while (0)

    LOAD_STAGE(0, kz);
    LOAD_STAGE(1, kz + 64);

    const int arow = wm * 64 + (lane & 7) + ((lane >> 3) & 1) * 8;
    const int acol = (lane >> 4);
    const int brow = wn * 32 + (lane & 7) + (lane >> 4) * 8;
    const int bcol = ((lane >> 3) & 1);

    for (int kt = 0; kt < 16; kt++) {
        CP_WAIT1();
        __syncthreads();
        uint32_t st = sb + (kt & 1) * 32768;
#pragma unroll
        for (int ks = 0; ks < 4; ks++) {
            uint32_t a[4][4], b[2][4];
#pragma unroll
            for (int mi = 0; mi < 4; mi++) {
                int r = arow + mi * 16;
                uint32_t off = ((uint32_t)(r * 128 + (acol + ks * 2) * 16)) ^ (((uint32_t)r & 7u) << 4);
                ldsm4(a[mi], st + off);
            }
#pragma unroll
            for (int nj = 0; nj < 2; nj++) {
                int r = brow + nj * 16;
                uint32_t off = ((uint32_t)(r * 128 + (bcol + ks * 2) * 16)) ^ (((uint32_t)r & 7u) << 4);
                ldsm4(b[nj], st + 16384 + off);
            }
#pragma unroll
            for (int mi = 0; mi < 4; mi++)
#pragma unroll
                for (int nf = 0; nf < 4; nf++)
                    mma_bf16(acc[mi][nf], a[mi], &b[nf >> 1][(nf & 1) * 2]);
        }
        __syncthreads();
        if (kt < 14) LOAD_STAGE(kt & 1, kz + (kt + 2) * 64);
        else CP_COMMIT();
    }
#undef LOAD_STAGE

#pragma unroll
    for (int mi = 0; mi < 4; mi++) {
        int r0 = bbase + wm * 64 + mi * 16 + (lane >> 2);
        float* p0 = g_partial + ((size_t)z * B_ + r0) * H_ + hbase;
        float* p1 = g_partial + ((size_t)z * B_ + r0 + 8) * H_ + hbase;
#pragma unroll
        for (int nf = 0; nf < 4; nf++) {
            int h0 = wn * 32 + nf * 8 + (lane & 3) * 2;
            *(float2*)(p0 + h0) = make_float2(acc[mi][nf][0], acc[mi][nf][1]);
            *(float2*)(p1 + h0) = make_float2(acc[mi][nf][2], acc[mi][nf][3]);
        }
    }
}

// ---------------- softmax with inline gumbel (+ bf16 probs) ----------------
__global__ void __launch_bounds__(1024) softmax_kernel(
    const float* __restrict__ out, float* __restrict__ outw,
    const void* __restrict__ taup, int t, int writeProbs) {
    __shared__ float sred[32];
    int b = blockIdx.x;
    const float* lrow = out + (((size_t)b * T_ + t) << 15);
    float* prow = outw + (size_t)B_ * T_ * V_ + (((size_t)b * T_ + t) << 15);
    __nv_bfloat16* brow = g_probs_bf16 + (size_t)b * V_;
    float inv_tau = 1.0f / tau_value(taup);
    float x[32];
    float m = -3.4e38f;
#pragma unroll
    for (int i = 0; i < 32; i++) {
        int v = threadIdx.x + i * 1024;
        float g = gumbel_val((unsigned)t, (unsigned)b, (unsigned)v);
        x[i] = (lrow[v] + g) * inv_tau;
        m = fmaxf(m, x[i]);
    }
    m = blockReduceMax(m, sred);
    float s = 0.f;
#pragma unroll
    for (int i = 0; i < 32; i++) {
        float e = expf(x[i] - m);
        x[i] = e;
        s += e;
    }
    s = blockReduceSum(s, sred);
    float r = 1.0f / s;
#pragma unroll
    for (int i = 0; i < 32; i++) {
        float p = x[i] * r;
        int v = threadIdx.x + i * 1024;
        if (writeProbs) prow[v] = p;
        brow[v] = __float2bfloat16(p);
    }
}

// ---------------- residual update + RMSNorm ----------------
__global__ void __launch_bounds__(512) update_kernel(
    const float* __restrict__ gamma, const float* __restrict__ rms_w, int t) {
    __shared__ float sred[32];
    int b = blockIdx.x, h = threadIdx.x;
    float e = 0.f;
#pragma unroll
    for (int s = 0; s < ZSPLIT; s++) e += g_partial[((size_t)s * B_ + b) * H_ + h];
    float eg = expf(gamma[t]);
    float hn = g_h[b * H_ + h] - eg * e;
    float ss = blockReduceSum(hn * hn, sred);
    float denom = sqrtf(ss * (1.0f / H_) + RMS_EPS);
    float hv = hn / denom * rms_w[h];
    g_h[b * H_ + h] = hv;
    __nv_bfloat16 hi = __float2bfloat16(hv);
    g_h_hi[b * H_ + h] = hi;
    g_h_lo[b * H_ + h] = __float2bfloat16(hv - __bfloat162float(hi));
    float n2 = blockReduceSum(hv * hv, sred);
    if (h == 0) g_zinv[b] = 1.0f / fmaxf(sqrtf(n2), 1e-12f);
}

// ---------------- launch ----------------
extern "C" void kernel_launch(void* const* d_in, const int* in_sizes, int n_in,
                              void* d_out, int out_size) {
    const float* x           = (const float*)d_in[0];
    const float* W1          = (const float*)d_in[1];
    const float* b1          = (const float*)d_in[2];
    const float* ln_g        = (const float*)d_in[3];
    const float* ln_b        = (const float*)d_in[4];
    const float* codebook    = (const float*)d_in[5];
    const float* logit_scale = (const float*)d_in[6];
    const float* gamma       = (const float*)d_in[7];
    const float* rms_w       = (const float*)d_in[8];
    const void*  tau         = d_in[9];
    float* out = (float*)d_out;

    cudaFuncSetAttribute(logits_mma_kernel, cudaFuncAttributeMaxDynamicSharedMemorySize, LG_SMEM);
    cudaFuncSetAttribute(expected_mma_kernel, cudaFuncAttributeMaxDynamicSharedMemorySize, EX_SMEM);

    const long long logitsElems = (long long)B_ * T_ * V_;
    int writeProbs = ((long long)out_size >= 2 * logitsElems) ? 1 : 0;

    backbone_kernel<<<B_, 512>>>(x, W1, b1, ln_g, ln_b);
    cinv_kernel<<<V_ / 8, 256>>>(codebook);
    prep_kernel<<<dim3(V_ / 32, H_ / 32), 256>>>(codebook);

    for (int t = 0; t < T_; t++) {
        logits_mma_kernel<<<dim3(2, V_ / 128), 256, LG_SMEM>>>(logit_scale, out, t);
        softmax_kernel<<<B_, 1024>>>(out, out, tau, t, writeProbs);
        if (t < T_ - 1) {
            expected_mma_kernel<<<dim3(H_ / 128, B_ / 128, ZSPLIT), 256, EX_SMEM>>>();
            update_kernel<<<B_, 512>>>(gamma, rms_w, t);
        }
    }
}

// round 6
// speedup vs baseline: 3.0671x; 1.0642x over previous
#include <cuda_runtime.h>
#include <cuda_bf16.h>
#include <cstdint>
#include <math.h>

// Problem constants
#define B_  256
#define E_  256
#define H_  512
#define V_  32768
#define T_  8
#define LN_EPS 1e-5f
#define RMS_EPS 1.1920928955078125e-7f   // finfo(f32).eps
#define TINY_F 1.17549435e-38f

#define ZSPLIT 32                         // split-K factor for expected GEMM

// ---------------- device scratch (static, allocation-free) ----------------
__device__ __align__(16) float g_h[B_ * H_];                 // residual h (fp32 exact)
__device__ __align__(16) __nv_bfloat16 g_h_hi[B_ * H_];
__device__ __align__(16) __nv_bfloat16 g_h_lo[B_ * H_];
__device__ float g_zinv[B_];
__device__ float g_cinv[V_];
__device__ __align__(16) __nv_bfloat16 g_C_hi[(size_t)V_ * H_];   // codebook hi  [V][H]
__device__ __align__(16) __nv_bfloat16 g_C_lo[(size_t)V_ * H_];   // codebook lo  [V][H]
__device__ __align__(16) __nv_bfloat16 g_CT[(size_t)H_ * V_];     // codebook^T bf16 [H][V]
__device__ __align__(16) __nv_bfloat16 g_probs_bf16[(size_t)B_ * V_];
__device__ __align__(16) float g_partial[ZSPLIT * B_ * H_];       // split-K partials

// ================= PTX helpers (base ISA only) =================
__device__ __forceinline__ uint32_t smem_u32(const void* p) {
    uint32_t a;
    asm("{ .reg .u64 t; cvta.to.shared.u64 t, %1; cvt.u32.u64 %0, t; }" : "=r"(a) : "l"(p));
    return a;
}
__device__ __forceinline__ void cp16(uint32_t dst, const void* src) {
    asm volatile("cp.async.cg.shared.global [%0], [%1], 16;" :: "r"(dst), "l"(src) : "memory");
}
#define CP_COMMIT() asm volatile("cp.async.commit_group;" ::: "memory")
#define CP_WAIT1()  asm volatile("cp.async.wait_group 1;" ::: "memory")

__device__ __forceinline__ void ldsm4(uint32_t* r, uint32_t addr) {
    asm volatile("ldmatrix.sync.aligned.m8n8.x4.shared.b16 {%0,%1,%2,%3}, [%4];"
                 : "=r"(r[0]), "=r"(r[1]), "=r"(r[2]), "=r"(r[3]) : "r"(addr));
}
__device__ __forceinline__ void mma_bf16(float* d, const uint32_t* a, const uint32_t* b) {
    asm volatile(
        "mma.sync.aligned.m16n8k16.row.col.f32.bf16.bf16.f32 "
        "{%0,%1,%2,%3}, {%4,%5,%6,%7}, {%8,%9}, {%0,%1,%2,%3};"
        : "+f"(d[0]), "+f"(d[1]), "+f"(d[2]), "+f"(d[3])
        : "r"(a[0]), "r"(a[1]), "r"(a[2]), "r"(a[3]), "r"(b[0]), "r"(b[1]));
}

// ---------------- reductions ----------------
__device__ __forceinline__ float blockReduceSum(float v, float* sh) {
    __syncthreads();
    int lane = threadIdx.x & 31, wid = threadIdx.x >> 5;
#pragma unroll
    for (int o = 16; o; o >>= 1) v += __shfl_xor_sync(0xFFFFFFFFu, v, o);
    if (lane == 0) sh[wid] = v;
    __syncthreads();
    int nw = blockDim.x >> 5;
    if (wid == 0) {
        float s = (lane < nw) ? sh[lane] : 0.f;
#pragma unroll
        for (int o = 16; o; o >>= 1) s += __shfl_xor_sync(0xFFFFFFFFu, s, o);
        if (lane == 0) sh[0] = s;
    }
    __syncthreads();
    float r = sh[0];
    __syncthreads();
    return r;
}
__device__ __forceinline__ float blockReduceMax(float v, float* sh) {
    __syncthreads();
    int lane = threadIdx.x & 31, wid = threadIdx.x >> 5;
#pragma unroll
    for (int o = 16; o; o >>= 1) v = fmaxf(v, __shfl_xor_sync(0xFFFFFFFFu, v, o));
    if (lane == 0) sh[wid] = v;
    __syncthreads();
    int nw = blockDim.x >> 5;
    if (wid == 0) {
        float s = (lane < nw) ? sh[lane] : -3.4e38f;
#pragma unroll
        for (int o = 16; o; o >>= 1) s = fmaxf(s, __shfl_xor_sync(0xFFFFFFFFu, s, o));
        if (lane == 0) sh[0] = s;
    }
    __syncthreads();
    float r = sh[0];
    __syncthreads();
    return r;
}

// ---------------- Threefry-2x32 (JAX partitionable, key=(0,42)) ----------------
__device__ __forceinline__ unsigned rotl32(unsigned x, int r) { return __funnelshift_l(x, x, r); }
__device__ __forceinline__ uint2 tf2x32(unsigned x0, unsigned x1) {
    const unsigned k0 = 0u, k1 = 42u;
    const unsigned k2 = k0 ^ k1 ^ 0x1BD11BDAu;
    x0 += k0; x1 += k1;
#define TFR(r) { x0 += x1; x1 = rotl32(x1, r); x1 ^= x0; }
    TFR(13) TFR(15) TFR(26) TFR(6)
    x0 += k1; x1 += k2 + 1u;
    TFR(17) TFR(29) TFR(16) TFR(24)
    x0 += k2; x1 += k0 + 2u;
    TFR(13) TFR(15) TFR(26) TFR(6)
    x0 += k0; x1 += k1 + 3u;
    TFR(17) TFR(29) TFR(16) TFR(24)
    x0 += k1; x1 += k2 + 4u;
    TFR(13) TFR(15) TFR(26) TFR(6)
    x0 += k2; x1 += k0 + 5u;
#undef TFR
    return make_uint2(x0, x1);
}
// gumbel = -log(-log(u)). Precision-critical region is u -> 1 where -log(u) -> 0.
// u is built as x - 1 with x in [1,2), so d = x - 2 is EXACT; for d > -1/16 use a
// log1p polynomial (rel trunc err <= 3e-6); else -__logf(u) has y >= 0.0645 so its
// 2^-21.4 abs error is <= 5.5e-6 relative. Outer -__logf(y) abs err ~5e-7. All safe.
__device__ __forceinline__ float gumbel_val(unsigned t, unsigned b, unsigned v) {
    unsigned f = (((t << 8) | b) << 15) | v;
    uint2 r = tf2x32(0u, f);
    unsigned bits = r.x ^ r.y;
    unsigned m = bits >> 9;
    float x = __uint_as_float(0x3F800000u | m);
    float u = x - 1.0f;                 // uniform in [0,1), exact
    float d = x - 2.0f;                 // u - 1, exact, in [-1, 0)
    // poly: -log1p(d) = -(d - d^2/2 + d^3/3 - d^4/4)
    float p = fmaf(-0.25f, d, 0.33333333f);
    p = fmaf(p, d, -0.5f);
    p = fmaf(p, d, 1.0f);
    p = -p * d;
    float l = -__logf(u);
    float y = (d > -0.0625f) ? p : l;
    y = (m == 0u) ? 87.3365448f : y;    // u = tiny path
    return -__logf(y);
}
__device__ __forceinline__ float tau_value(const void* p) {
    int i = *(const int*)p;
    float f = __int_as_float(i);
    if (f > 1e-3f && f < 1e6f) return f;
    return (float)i;
}

// ---------------- backbone: h = GELU(LN(x@W1 + b1)) ----------------
__global__ void __launch_bounds__(512) backbone_kernel(
    const float* __restrict__ x, const float* __restrict__ W1,
    const float* __restrict__ b1, const float* __restrict__ ln_g,
    const float* __restrict__ ln_b) {
    __shared__ float xs[E_];
    __shared__ float sred[32];
    int b = blockIdx.x, col = threadIdx.x;
    if (col < E_) xs[col] = x[b * E_ + col];
    __syncthreads();
    float acc = b1[col];
#pragma unroll 4
    for (int e = 0; e < E_; e++) acc = fmaf(xs[e], W1[e * H_ + col], acc);
    float mu = blockReduceSum(acc, sred) * (1.0f / H_);
    float d = acc - mu;
    float var = blockReduceSum(d * d, sred) * (1.0f / H_);
    float nrm = d / sqrtf(var + LN_EPS) * ln_g[col] + ln_b[col];
    float hv = 0.5f * nrm * (1.0f + erff(nrm * 0.70710678118654752f));
    g_h[b * H_ + col] = hv;
    __nv_bfloat16 hi = __float2bfloat16(hv);
    g_h_hi[b * H_ + col] = hi;
    g_h_lo[b * H_ + col] = __float2bfloat16(hv - __bfloat162float(hi));
    float n2 = blockReduceSum(hv * hv, sred);
    if (col == 0) g_zinv[b] = 1.0f / fmaxf(sqrtf(n2), 1e-12f);
}

// ---------------- codebook row inverse norms ----------------
__global__ void __launch_bounds__(256) cinv_kernel(const float* __restrict__ C) {
    int warp = blockIdx.x * 8 + (threadIdx.x >> 5);
    int lane = threadIdx.x & 31;
    if (warp >= V_) return;
    const float* row = C + (size_t)warp * H_;
    float ss = 0.f;
#pragma unroll 4
    for (int i = lane; i < H_; i += 32) { float v = row[i]; ss = fmaf(v, v, ss); }
#pragma unroll
    for (int o = 16; o; o >>= 1) ss += __shfl_xor_sync(0xFFFFFFFFu, ss, o);
    if (lane == 0) g_cinv[warp] = 1.0f / fmaxf(sqrtf(ss), 1e-12f);
}

// ---------------- codebook prep: bf16 hi/lo + bf16 transpose ----------------
__global__ void __launch_bounds__(256) prep_kernel(const float* __restrict__ C) {
    __shared__ float tile[32][33];
    int v0 = blockIdx.x * 32, h0 = blockIdx.y * 32;
    int tx = threadIdx.x & 31, ty = threadIdx.x >> 5;
#pragma unroll
    for (int j = 0; j < 4; j++) {
        int v = v0 + ty + j * 8;
        float val = C[(size_t)v * H_ + h0 + tx];
        __nv_bfloat16 hi = __float2bfloat16(val);
        g_C_hi[(size_t)v * H_ + h0 + tx] = hi;
        g_C_lo[(size_t)v * H_ + h0 + tx] = __float2bfloat16(val - __bfloat162float(hi));
        tile[ty + j * 8][tx] = val;
    }
    __syncthreads();
#pragma unroll
    for (int j = 0; j < 4; j++) {
        int h = h0 + ty + j * 8;
        g_CT[(size_t)h * V_ + v0 + tx] = __float2bfloat16(tile[tx][ty + j * 8]);
    }
}

// ================= logits GEMM (mma.sync bf16, hi/lo 3-pass) =================
// Tile 128b x 64v per CTA. stage = Ah 16K | Al 16K | Bh 8K | Bl 8K = 48KB, 2 stages.
// 96KB smem + <=128 regs -> 2 CTAs/SM for latency hiding.
#define LG_STAGE 49152
#define LG_SMEM (2 * LG_STAGE)
__global__ void __launch_bounds__(256, 2) logits_mma_kernel(
    const float* __restrict__ lscale, float* __restrict__ out, int t) {
    extern __shared__ char smem[];
    const uint32_t sb = smem_u32(smem);
    const int tid = threadIdx.x, lane = tid & 31, wid = tid >> 5;
    const int wm = wid >> 1, wn = wid & 1;      // 4m x 2n warps, warp tile 32x32
    const int bbase = blockIdx.x * 128, vbase = blockIdx.y * 64;

    float acc[2][4][4];
#pragma unroll
    for (int i = 0; i < 2; i++)
#pragma unroll
        for (int j = 0; j < 4; j++)
#pragma unroll
            for (int c = 0; c < 4; c++) acc[i][j][c] = 0.f;

    const int lr = tid >> 3;            // 0..31
    const int lc = tid & 7;             // 16B chunk col

#define LOAD_STAGE(s, k0) do { \
        uint32_t st_ = sb + (s) * LG_STAGE; \
        _Pragma("unroll") \
        for (int i_ = 0; i_ < 4; i_++) { \
            int r_ = lr + i_ * 32; \
            uint32_t sw_ = ((uint32_t)(r_ * 128 + lc * 16)) ^ (((uint32_t)r_ & 7u) << 4); \
            size_t ga_ = (size_t)(bbase + r_) * H_ + (k0) + lc * 8; \
            cp16(st_ + sw_,         g_h_hi + ga_); \
            cp16(st_ + 16384 + sw_, g_h_lo + ga_); \
        } \
        _Pragma("unroll") \
        for (int i_ = 0; i_ < 2; i_++) { \
            int r_ = lr + i_ * 32; \
            uint32_t sw_ = ((uint32_t)(r_ * 128 + lc * 16)) ^ (((uint32_t)r_ & 7u) << 4); \
            size_t gb_ = (size_t)(vbase + r_) * H_ + (k0) + lc * 8; \
            cp16(st_ + 32768 + sw_, g_C_hi + gb_); \
            cp16(st_ + 40960 + sw_, g_C_lo + gb_); \
        } \
        CP_COMMIT(); \
    } while (0)

    LOAD_STAGE(0, 0);
    LOAD_STAGE(1, 64);

    const int arow = wm * 32 + (lane & 7) + ((lane >> 3) & 1) * 8;  // + mi*16
    const int acol = (lane >> 4);                                    // + ks*2
    const int brow = wn * 32 + (lane & 7) + (lane >> 4) * 8;         // + nj*16
    const int bcol = ((lane >> 3) & 1);                              // + ks*2

    for (int kt = 0; kt < 8; kt++) {
        CP_WAIT1();
        __syncthreads();
        uint32_t st = sb + (kt & 1) * LG_STAGE;
#pragma unroll
        for (int ks = 0; ks < 4; ks++) {
            uint32_t ah[2][4], al[2][4], bh[2][4], bl[2][4];
#pragma unroll
            for (int mi = 0; mi < 2; mi++) {
                int r = arow + mi * 16;
                uint32_t off = ((uint32_t)(r * 128 + (acol + ks * 2) * 16)) ^ (((uint32_t)r & 7u) << 4);
                ldsm4(ah[mi], st + off);
                ldsm4(al[mi], st + 16384 + off);
            }
#pragma unroll
            for (int nj = 0; nj < 2; nj++) {
                int r = brow + nj * 16;
                uint32_t off = ((uint32_t)(r * 128 + (bcol + ks * 2) * 16)) ^ (((uint32_t)r & 7u) << 4);
                ldsm4(bh[nj], st + 32768 + off);
                ldsm4(bl[nj], st + 40960 + off);
            }
#pragma unroll
            for (int mi = 0; mi < 2; mi++)
#pragma unroll
                for (int nf = 0; nf < 4; nf++) {
                    const uint32_t* bhp = &bh[nf >> 1][(nf & 1) * 2];
                    const uint32_t* blp = &bl[nf >> 1][(nf & 1) * 2];
                    mma_bf16(acc[mi][nf], ah[mi], bhp);
                    mma_bf16(acc[mi][nf], ah[mi], blp);
                    mma_bf16(acc[mi][nf], al[mi], bhp);
                }
        }
        __syncthreads();
        if (kt < 6) LOAD_STAGE(kt & 1, (kt + 2) * 64);
        else CP_COMMIT();  // keep wait_group accounting aligned
    }
#undef LOAD_STAGE

    // epilogue
    float scale = expf(__ldg(lscale + t));
#pragma unroll
    for (int mi = 0; mi < 2; mi++) {
        int r0 = bbase + wm * 32 + mi * 16 + (lane >> 2);
        float z0 = g_zinv[r0], z1 = g_zinv[r0 + 8];
        float* row0 = out + (((size_t)r0 * T_ + t) << 15);
        float* row1 = out + (((size_t)(r0 + 8) * T_ + t) << 15);
#pragma unroll
        for (int nf = 0; nf < 4; nf++) {
            int v0 = vbase + wn * 32 + nf * 8 + (lane & 3) * 2;
            float cv0 = g_cinv[v0] * scale, cv1 = g_cinv[v0 + 1] * scale;
            float2 w0 = make_float2(acc[mi][nf][0] * z0 * cv0, acc[mi][nf][1] * z0 * cv1);
            float2 w1 = make_float2(acc[mi][nf][2] * z1 * cv0, acc[mi][nf][3] * z1 * cv1);
            *(float2*)(row0 + v0) = w0;
            *(float2*)(row1 + v0) = w1;
        }
    }
}

// ================= expected GEMM (mma.sync bf16, split-K=32) =================
// Tile 128b x 64h per CTA; K-slice 1024 per z. stage = A 16K | B 8K = 24KB, 2 stages.
#define EX_STAGE 24576
#define EX_SMEM (2 * EX_STAGE)
__global__ void __launch_bounds__(256, 2) expected_mma_kernel() {
    extern __shared__ char smem[];
    const uint32_t sb = smem_u32(smem);
    const int tid = threadIdx.x, lane = tid & 31, wid = tid >> 5;
    const int wm = wid >> 1, wn = wid & 1;
    const int hbase = blockIdx.x * 64, bbase = blockIdx.y * 128;
    const int z = blockIdx.z;
    const int kz = z * (V_ / ZSPLIT);   // 1024

    float acc[2][4][4];
#pragma unroll
    for (int i = 0; i < 2; i++)
#pragma unroll
        for (int j = 0; j < 4; j++)
#pragma unroll
            for (int c = 0; c < 4; c++) acc[i][j][c] = 0.f;

    const int lr = tid >> 3;
    const int lc = tid & 7;

#define LOAD_STAGE(s, k0) do { \
        uint32_t st_ = sb + (s) * EX_STAGE; \
        _Pragma("unroll") \
        for (int i_ = 0; i_ < 4; i_++) { \
            int r_ = lr + i_ * 32; \
            uint32_t sw_ = ((uint32_t)(r_ * 128 + lc * 16)) ^ (((uint32_t)r_ & 7u) << 4); \
            cp16(st_ + sw_, g_probs_bf16 + (size_t)(bbase + r_) * V_ + (k0) + lc * 8); \
        } \
        _Pragma("unroll") \
        for (int i_ = 0; i_ < 2; i_++) { \
            int r_ = lr + i_ * 32; \
            uint32_t sw_ = ((uint32_t)(r_ * 128 + lc * 16)) ^ (((uint32_t)r_ & 7u) << 4); \
            cp16(st_ + 16384 + sw_, g_CT + (size_t)(hbase + r_) * V_ + (k0) + lc * 8); \
        } \
        CP_COMMIT(); \
    } while (0)

    LOAD_STAGE(0, kz);
    LOAD_STAGE(1, kz + 64);

    const int arow = wm * 32 + (lane & 7) + ((lane >> 3) & 1) * 8;
    const int acol = (lane >> 4);
    const int brow = wn * 32 + (lane & 7) + (lane >> 4) * 8;
    const int bcol = ((lane >> 3) & 1);

    for (int kt = 0; kt < 16; kt++) {
        CP_WAIT1();
        __syncthreads();
        uint32_t st = sb + (kt & 1) * EX_STAGE;
#pragma unroll
        for (int ks = 0; ks < 4; ks++) {
            uint32_t a[2][4], b[2][4];
#pragma unroll
            for (int mi = 0; mi < 2; mi++) {
                int r = arow + mi * 16;
                uint32_t off = ((uint32_t)(r * 128 + (acol + ks * 2) * 16)) ^ (((uint32_t)r & 7u) << 4);
                ldsm4(a[mi], st + off);
            }
#pragma unroll
            for (int nj = 0; nj < 2; nj++) {
                int r = brow + nj * 16;
                uint32_t off = ((uint32_t)(r * 128 + (bcol + ks * 2) * 16)) ^ (((uint32_t)r & 7u) << 4);
                ldsm4(b[nj], st + 16384 + off);
            }
#pragma unroll
            for (int mi = 0; mi < 2; mi++)
#pragma unroll
                for (int nf = 0; nf < 4; nf++)
                    mma_bf16(acc[mi][nf], a[mi], &b[nf >> 1][(nf & 1) * 2]);
        }
        __syncthreads();
        if (kt < 14) LOAD_STAGE(kt & 1, kz + (kt + 2) * 64);
        else CP_COMMIT();
    }
#undef LOAD_STAGE

#pragma unroll
    for (int mi = 0; mi < 2; mi++) {
        int r0 = bbase + wm * 32 + mi * 16 + (lane >> 2);
        float* p0 = g_partial + ((size_t)z * B_ + r0) * H_ + hbase;
        float* p1 = g_partial + ((size_t)z * B_ + r0 + 8) * H_ + hbase;
#pragma unroll
        for (int nf = 0; nf < 4; nf++) {
            int h0 = wn * 32 + nf * 8 + (lane & 3) * 2;
            *(float2*)(p0 + h0) = make_float2(acc[mi][nf][0], acc[mi][nf][1]);
            *(float2*)(p1 + h0) = make_float2(acc[mi][nf][2], acc[mi][nf][3]);
        }
    }
}

// ---------------- softmax with inline gumbel (+ bf16 probs) ----------------
__global__ void __launch_bounds__(1024) softmax_kernel(
    const float* __restrict__ out, float* __restrict__ outw,
    const void* __restrict__ taup, int t, int writeProbs) {
    __shared__ float sred[32];
    int b = blockIdx.x;
    const float* lrow = out + (((size_t)b * T_ + t) << 15);
    float* prow = outw + (size_t)B_ * T_ * V_ + (((size_t)b * T_ + t) << 15);
    __nv_bfloat16* brow = g_probs_bf16 + (size_t)b * V_;
    float inv_tau = 1.0f / tau_value(taup);
    float x[32];
    float m = -3.4e38f;
#pragma unroll
    for (int i = 0; i < 32; i++) {
        int v = threadIdx.x + i * 1024;
        float g = gumbel_val((unsigned)t, (unsigned)b, (unsigned)v);
        x[i] = (lrow[v] + g) * inv_tau;
        m = fmaxf(m, x[i]);
    }
    m = blockReduceMax(m, sred);
    float s = 0.f;
#pragma unroll
    for (int i = 0; i < 32; i++) {
        float e = __expf(x[i] - m);
        x[i] = e;
        s += e;
    }
    s = blockReduceSum(s, sred);
    float r = 1.0f / s;
#pragma unroll
    for (int i = 0; i < 32; i++) {
        float p = x[i] * r;
        int v = threadIdx.x + i * 1024;
        if (writeProbs) prow[v] = p;
        brow[v] = __float2bfloat16(p);
    }
}

// ---------------- residual update + RMSNorm ----------------
__global__ void __launch_bounds__(512) update_kernel(
    const float* __restrict__ gamma, const float* __restrict__ rms_w, int t) {
    __shared__ float sred[32];
    int b = blockIdx.x, h = threadIdx.x;
    float e = 0.f;
#pragma unroll
    for (int s = 0; s < ZSPLIT; s++) e += g_partial[((size_t)s * B_ + b) * H_ + h];
    float eg = expf(gamma[t]);
    float hn = g_h[b * H_ + h] - eg * e;
    float ss = blockReduceSum(hn * hn, sred);
    float denom = sqrtf(ss * (1.0f / H_) + RMS_EPS);
    float hv = hn / denom * rms_w[h];
    g_h[b * H_ + h] = hv;
    __nv_bfloat16 hi = __float2bfloat16(hv);
    g_h_hi[b * H_ + h] = hi;
    g_h_lo[b * H_ + h] = __float2bfloat16(hv - __bfloat162float(hi));
    float n2 = blockReduceSum(hv * hv, sred);
    if (h == 0) g_zinv[b] = 1.0f / fmaxf(sqrtf(n2), 1e-12f);
}

// ---------------- launch ----------------
extern "C" void kernel_launch(void* const* d_in, const int* in_sizes, int n_in,
                              void* d_out, int out_size) {
    const float* x           = (const float*)d_in[0];
    const float* W1          = (const float*)d_in[1];
    const float* b1          = (const float*)d_in[2];
    const float* ln_g        = (const float*)d_in[3];
    const float* ln_b        = (const float*)d_in[4];
    const float* codebook    = (const float*)d_in[5];
    const float* logit_scale = (const float*)d_in[6];
    const float* gamma       = (const float*)d_in[7];
    const float* rms_w       = (const float*)d_in[8];
    const void*  tau         = d_in[9];
    float* out = (float*)d_out;

    cudaFuncSetAttribute(logits_mma_kernel, cudaFuncAttributeMaxDynamicSharedMemorySize, LG_SMEM);
    cudaFuncSetAttribute(expected_mma_kernel, cudaFuncAttributeMaxDynamicSharedMemorySize, EX_SMEM);

    const long long logitsElems = (long long)B_ * T_ * V_;
    int writeProbs = ((long long)out_size >= 2 * logitsElems) ? 1 : 0;

    backbone_kernel<<<B_, 512>>>(x, W1, b1, ln_g, ln_b);
    cinv_kernel<<<V_ / 8, 256>>>(codebook);
    prep_kernel<<<dim3(V_ / 32, H_ / 32), 256>>>(codebook);

    for (int t = 0; t < T_; t++) {
        logits_mma_kernel<<<dim3(B_ / 128, V_ / 64), 256, LG_SMEM>>>(logit_scale, out, t);
        softmax_kernel<<<B_, 1024>>>(out, out, tau, t, writeProbs);
        if (t < T_ - 1) {
            expected_mma_kernel<<<dim3(H_ / 64, B_ / 128, ZSPLIT), 256, EX_SMEM>>>();
            update_kernel<<<B_, 512>>>(gamma, rms_w, t);
        }
    }
}